// round 14
// baseline (speedup 1.0000x reference)
#include <cuda_runtime.h>
#include <cuda_fp16.h>
#include <math.h>
#include <stdint.h>

// ---------------- problem constants ----------------
#define EE   1024
#define HID  4096
#define MM   8192            // B*N rows
#define CH   4096            // rows per chunk (2 batches; attention is batch-local)

// ---------------- scratch (device globals; no allocation) ----------------
__device__ __align__(128) __half g_xh  [(size_t)MM * EE];
__device__ __align__(128) __half g_wq  [(size_t)3 * EE * EE];
__device__ __align__(128) __half g_wo  [(size_t)EE * EE];
__device__ __align__(128) __half g_w1  [(size_t)HID * EE];
__device__ __align__(128) __half g_w2  [(size_t)EE * HID];
__device__ __align__(128) __half g_qkvh[(size_t)MM * 3 * EE];
__device__ __align__(128) __half g_ah  [(size_t)MM * EE];
__device__ __align__(128) float  g_res1[(size_t)MM * EE];
__device__ __align__(128) float  g_hf  [(size_t)MM * EE];
__device__ __align__(128) __half g_hh  [(size_t)MM * EE];
__device__ __align__(128) __half g_fh  [(size_t)MM * HID];
__device__ __align__(128) float  g_res2[(size_t)MM * EE];

// ---------------- helpers ----------------
__device__ __forceinline__ void ldsm4(uint32_t& r0, uint32_t& r1, uint32_t& r2, uint32_t& r3,
                                      uint32_t a) {
    asm volatile("ldmatrix.sync.aligned.m8n8.x4.shared.b16 {%0,%1,%2,%3}, [%4];"
                 : "=r"(r0), "=r"(r1), "=r"(r2), "=r"(r3) : "r"(a));
}
__device__ __forceinline__ void mma16816(float* c, const uint32_t* a, const uint32_t* b) {
    asm volatile(
        "mma.sync.aligned.m16n8k16.row.col.f32.f16.f16.f32 "
        "{%0,%1,%2,%3}, {%4,%5,%6,%7}, {%8,%9}, {%0,%1,%2,%3};"
        : "+f"(c[0]), "+f"(c[1]), "+f"(c[2]), "+f"(c[3])
        : "r"(a[0]), "r"(a[1]), "r"(a[2]), "r"(a[3]), "r"(b[0]), "r"(b[1]));
}
__device__ __forceinline__ void cp16(uint32_t dst, const void* src) {
    asm volatile("cp.async.cg.shared.global [%0], [%1], 16;" :: "r"(dst), "l"(src));
}
__device__ __forceinline__ void cp_commit() { asm volatile("cp.async.commit_group;"); }
template <int N>
__device__ __forceinline__ void cp_wait() { asm volatile("cp.async.wait_group %0;" :: "n"(N)); }

// swizzled 16B-chunk offset within [rows x 64half] smem region (row-major 128B rows)
__device__ __forceinline__ uint32_t swoff(uint32_t r, uint32_t c) {
    return ((r << 3) + (c ^ (r & 7))) << 4;
}

// ---------------- fp32 -> fp16 conversion (single region) ----------------
__global__ __launch_bounds__(256) void to_half(
    const float* __restrict__ src, __half* __restrict__ dst, size_t total8)
{
    size_t idx = (size_t)blockIdx.x * blockDim.x + threadIdx.x;
    if (idx >= total8) return;
    const float4 v0 = reinterpret_cast<const float4*>(src)[idx * 2];
    const float4 v1 = reinterpret_cast<const float4*>(src)[idx * 2 + 1];
    __align__(16) __half hh[8];
    hh[0] = __float2half_rn(v0.x); hh[1] = __float2half_rn(v0.y);
    hh[2] = __float2half_rn(v0.z); hh[3] = __float2half_rn(v0.w);
    hh[4] = __float2half_rn(v1.x); hh[5] = __float2half_rn(v1.y);
    hh[6] = __float2half_rn(v1.z); hh[7] = __float2half_rn(v1.w);
    reinterpret_cast<uint4*>(dst)[idx] = *reinterpret_cast<uint4*>(hh);
}

// ---------------- fused fp32 -> fp16 conversion (two regions, one launch) ----------------
__global__ __launch_bounds__(256) void to_half2(
    const float* __restrict__ sa, __half* __restrict__ da, size_t a8,
    const float* __restrict__ sb, __half* __restrict__ db, size_t b8)
{
    size_t idx = (size_t)blockIdx.x * blockDim.x + threadIdx.x;
    const float* src; __half* dst;
    if (idx < a8)            { src = sa; dst = da; }
    else if (idx < a8 + b8)  { src = sb; dst = db; idx -= a8; }
    else return;
    const float4 v0 = reinterpret_cast<const float4*>(src)[idx * 2];
    const float4 v1 = reinterpret_cast<const float4*>(src)[idx * 2 + 1];
    __align__(16) __half hh[8];
    hh[0] = __float2half_rn(v0.x); hh[1] = __float2half_rn(v0.y);
    hh[2] = __float2half_rn(v0.z); hh[3] = __float2half_rn(v0.w);
    hh[4] = __float2half_rn(v1.x); hh[5] = __float2half_rn(v1.y);
    hh[6] = __float2half_rn(v1.z); hh[7] = __float2half_rn(v1.w);
    reinterpret_cast<uint4*>(dst)[idx] = *reinterpret_cast<uint4*>(hh);
}

// ---------------- persistent fp16 tensor-core GEMM: C[M,N] = A[M,K] * B[N,K]^T ----------------
// Tile 128x128, BK=64, 3 stages, 2 CTAs/SM. 8 warps as 2(M) x 4(N), warp 64x32.
// CTAs grid-stride over output tiles (kills wave-quantization tails).
// EPI 1: +bias,GELU -> Ch ; EPI 2: +bias + fp32 res -> Cf ; EPI 3: +bias -> Ch
#define STG_BYTES 32768
#define SMEM_GEMM (3 * STG_BYTES)

template <int EPI>
__global__ __launch_bounds__(256, 2) void gemm_mma(
    const __half* __restrict__ A, const __half* __restrict__ B,
    const float* __restrict__ bias, const float* __restrict__ res,
    float* __restrict__ Cf, __half* __restrict__ Ch,
    int N, int K, int ntx, int ntiles)
{
    extern __shared__ __align__(128) char smem[];
    const uint32_t sb = (uint32_t)__cvta_generic_to_shared(smem);

    const int tid  = threadIdx.x;
    const int lane = tid & 31;
    const int wid  = tid >> 5;
    const int wm   = wid & 1;
    const int wn   = wid >> 1;
    const int T    = K >> 6;

    for (int tile = blockIdx.x; tile < ntiles; tile += gridDim.x) {
        const int mblk = (tile / ntx) * 128;
        const int nblk = (tile % ntx) * 128;

        float acc[4][4][4];
#pragma unroll
        for (int i = 0; i < 4; ++i)
#pragma unroll
            for (int j = 0; j < 4; ++j)
#pragma unroll
                for (int q = 0; q < 4; ++q) acc[i][j][q] = 0.f;

        auto load_stage = [&](int s, int kc) {
            const uint32_t base = sb + s * STG_BYTES;
            const int k0 = kc * 64;
#pragma unroll
            for (int i = 0; i < 4; ++i) {               // A: 128 rows
                const int id  = tid + i * 256;
                const int row = id >> 3;
                const int c   = id & 7;
                cp16(base + swoff(row, c), A + (size_t)(mblk + row) * K + k0 + c * 8);
            }
#pragma unroll
            for (int i = 0; i < 4; ++i) {               // B: 128 rows
                const int id  = tid + i * 256;
                const int row = id >> 3;
                const int c   = id & 7;
                cp16(base + 16384 + swoff(row, c), B + (size_t)(nblk + row) * K + k0 + c * 8);
            }
        };

        load_stage(0, 0); cp_commit();
        load_stage(1, 1); cp_commit();

        for (int t = 0; t < T; ++t) {
            cp_wait<1>();
            __syncthreads();
            if (t + 2 < T) load_stage((t + 2) % 3, t + 2);
            cp_commit();

            const uint32_t stA = sb + (t % 3) * STG_BYTES;
            const uint32_t stB = stA + 16384;

#pragma unroll
            for (int ks = 0; ks < 4; ++ks) {
                uint32_t a[4][4], b[4][2];
                const uint32_t arow = wm * 64 + (lane & 15);
                const uint32_t acol = ks * 2 + (lane >> 4);
#pragma unroll
                for (int mi = 0; mi < 4; ++mi) {
                    const uint32_t off = swoff(arow + mi * 16, acol);
                    ldsm4(a[mi][0], a[mi][1], a[mi][2], a[mi][3], stA + off);
                }
                const uint32_t brow = wn * 32 + (lane & 7) + ((lane >> 4) << 3);
                const uint32_t bcol = ks * 2 + ((lane >> 3) & 1);
#pragma unroll
                for (int pi = 0; pi < 2; ++pi) {
                    const uint32_t off = swoff(brow + pi * 16, bcol);
                    ldsm4(b[2 * pi][0], b[2 * pi][1], b[2 * pi + 1][0], b[2 * pi + 1][1],
                          stB + off);
                }
#pragma unroll
                for (int mi = 0; mi < 4; ++mi)
#pragma unroll
                    for (int ni = 0; ni < 4; ++ni) mma16816(acc[mi][ni], a[mi], b[ni]);
            }
        }
        cp_wait<0>();
        __syncthreads();    // all reads done before next tile's loads reuse buffers

        // -------- epilogue --------
#pragma unroll
        for (int mi = 0; mi < 4; ++mi) {
#pragma unroll
            for (int ni = 0; ni < 4; ++ni) {
                const int n = nblk + wn * 32 + ni * 8 + (lane & 3) * 2;
                const float b0 = bias[n], b1 = bias[n + 1];
                const int m0 = mblk + wm * 64 + mi * 16 + (lane >> 2);
#pragma unroll
                for (int half = 0; half < 2; ++half) {
                    const int m = m0 + half * 8;
                    float v0 = acc[mi][ni][half * 2 + 0] + b0;
                    float v1 = acc[mi][ni][half * 2 + 1] + b1;
                    if (EPI == 2) {
                        const float2 rv = *reinterpret_cast<const float2*>(
                            res + (size_t)m * N + n);
                        v0 += rv.x; v1 += rv.y;
                        *reinterpret_cast<float2*>(Cf + (size_t)m * N + n) =
                            make_float2(v0, v1);
                    } else {
                        if (EPI == 1) {
                            v0 = 0.5f * v0 * (1.0f + erff(v0 * 0.70710678118654752f));
                            v1 = 0.5f * v1 * (1.0f + erff(v1 * 0.70710678118654752f));
                        }
                        __half2 h2;
                        h2.x = __float2half_rn(v0);
                        h2.y = __float2half_rn(v1);
                        *reinterpret_cast<__half2*>(Ch + (size_t)m * N + n) = h2;
                    }
                }
            }
        }
    }
}

// ---------------- per-token head-softmax attention (chunk-local) ----------------
__global__ __launch_bounds__(128) void attn_kernel(
    const __half* __restrict__ qkv, __half* __restrict__ ahi)
{
    __shared__ float sq[3 * EE];
    __shared__ float sa[16][17];

    const int loc = blockIdx.x;          // local row in chunk
    const int bb  = loc >> 11;           // batch within chunk
    const int t   = loc & 2047;          // token within batch
    const int tid = threadIdx.x;

    const uint4* src = reinterpret_cast<const uint4*>(qkv + (size_t)loc * (3 * EE));
#pragma unroll
    for (int i = tid; i < 384; i += 128) {
        const uint4 pk = src[i];
        const __half* hp = reinterpret_cast<const __half*>(&pk);
        float* dp = sq + i * 8;
#pragma unroll
        for (int j = 0; j < 8; ++j) dp[j] = __half2float(hp[j]);
    }
    __syncthreads();

#pragma unroll
    for (int e = tid; e < 256; e += 128) {
        const int i = e >> 4, j = e & 15;
        const float* qi = sq + i * 64;
        const float* kj = sq + EE + j * 64;
        float dot = 0.f;
#pragma unroll
        for (int d = 0; d < 64; ++d) dot += qi[d] * kj[d];
        sa[i][j] = dot * 0.03125f;   // / sqrt(E)=32
    }
    __syncthreads();

    if (tid < 16) {
        float mx = -1e30f;
#pragma unroll
        for (int j = 0; j < 16; ++j) mx = fmaxf(mx, sa[tid][j]);
        float ex[16], s = 0.f;
#pragma unroll
        for (int j = 0; j < 16; ++j) { ex[j] = expf(sa[tid][j] - mx); s += ex[j]; }
        const float inv = 1.0f / s;
#pragma unroll
        for (int j = 0; j < 16; ++j) sa[tid][j] = ex[j] * inv;
    }
    __syncthreads();

    const int i  = tid >> 3;
    const int db = (tid & 7) * 8;
    float o[8] = {0.f, 0.f, 0.f, 0.f, 0.f, 0.f, 0.f, 0.f};
#pragma unroll
    for (int j = 0; j < 16; ++j) {
        const float a = sa[i][j];
        const float* vj = sq + 2 * EE + j * 64 + db;
#pragma unroll
        for (int p = 0; p < 8; ++p) o[p] += a * vj[p];
    }
    // scrambled target within batch: row = i*128 + t/16, col = (t%16)*64 + db
    const int m = bb * 2048 + i * 128 + (t >> 4);
    const int c = ((t & 15) << 6) + db;
    __align__(16) __half hh[8];
#pragma unroll
    for (int p = 0; p < 8; ++p) hh[p] = __float2half_rn(o[p]);
    *reinterpret_cast<uint4*>(ahi + (size_t)m * EE + c) = *reinterpret_cast<uint4*>(hh);
}

// ---------------- row LayerNorm over 1024 fp32 inputs ----------------
template <bool EMIT_HALF>
__global__ __launch_bounds__(256) void ln_kernel(
    const float* __restrict__ in, const float* __restrict__ g, const float* __restrict__ b,
    float* __restrict__ outf, __half* __restrict__ oh)
{
    __shared__ float red[8];
    __shared__ float s_mean, s_rstd;
    const int row = blockIdx.x;
    const int tid = threadIdx.x;

    const float4 v = reinterpret_cast<const float4*>(in + (size_t)row * EE)[tid];

    float s = v.x + v.y + v.z + v.w;
#pragma unroll
    for (int o = 16; o; o >>= 1) s += __shfl_xor_sync(0xffffffffu, s, o);
    if ((tid & 31) == 0) red[tid >> 5] = s;
    __syncthreads();
    if (tid == 0) {
        float tt = 0.f;
#pragma unroll
        for (int i = 0; i < 8; ++i) tt += red[i];
        s_mean = tt * (1.0f / 1024.0f);
    }
    __syncthreads();
    const float mean = s_mean;

    const float dx = v.x - mean, dy = v.y - mean, dz = v.z - mean, dw = v.w - mean;
    float sq = dx * dx + dy * dy + dz * dz + dw * dw;
#pragma unroll
    for (int o = 16; o; o >>= 1) sq += __shfl_xor_sync(0xffffffffu, sq, o);
    if ((tid & 31) == 0) red[tid >> 5] = sq;
    __syncthreads();
    if (tid == 0) {
        float tt = 0.f;
#pragma unroll
        for (int i = 0; i < 8; ++i) tt += red[i];
        s_rstd = rsqrtf(tt * (1.0f / 1024.0f) + 1e-5f);
    }
    __syncthreads();
    const float rstd = s_rstd;

    const float4 gg = reinterpret_cast<const float4*>(g)[tid];
    const float4 bb = reinterpret_cast<const float4*>(b)[tid];
    float4 o4;
    o4.x = dx * rstd * gg.x + bb.x;
    o4.y = dy * rstd * gg.y + bb.y;
    o4.z = dz * rstd * gg.z + bb.z;
    o4.w = dw * rstd * gg.w + bb.w;
    reinterpret_cast<float4*>(outf + (size_t)row * EE)[tid] = o4;

    if (EMIT_HALF) {
        __align__(8) __half hh4[4];
        hh4[0] = __float2half_rn(o4.x); hh4[1] = __float2half_rn(o4.y);
        hh4[2] = __float2half_rn(o4.z); hh4[3] = __float2half_rn(o4.w);
        *reinterpret_cast<uint2*>(oh + (size_t)row * EE + tid * 4) =
            *reinterpret_cast<uint2*>(hh4);
    }
}

// ---------------- launcher ----------------
#define PERSIST_GRID 296   // 148 SMs x 2 CTAs

extern "C" void kernel_launch(void* const* d_in, const int* in_sizes, int n_in,
                              void* d_out, int out_size)
{
    (void)in_sizes; (void)n_in; (void)out_size;
    const float* x     = (const float*)d_in[0];
    const float* Wqkv  = (const float*)d_in[1];
    const float* bqkv  = (const float*)d_in[2];
    const float* Wo    = (const float*)d_in[3];
    const float* bo    = (const float*)d_in[4];
    const float* ln1_g = (const float*)d_in[5];
    const float* ln1_b = (const float*)d_in[6];
    const float* W1    = (const float*)d_in[7];
    const float* bf1   = (const float*)d_in[8];
    const float* W2    = (const float*)d_in[9];
    const float* bf2   = (const float*)d_in[10];
    const float* ln2_g = (const float*)d_in[11];
    const float* ln2_b = (const float*)d_in[12];
    float* out = (float*)d_out;

    static cudaStream_t s_w = nullptr, s_b2 = nullptr;
    static cudaEvent_t ev_root, ev_cvt, ev_wo, ev_w1, ev_w2, ev_done1;
    if (!s_w) {
        cudaFuncSetAttribute(gemm_mma<1>, cudaFuncAttributeMaxDynamicSharedMemorySize, SMEM_GEMM);
        cudaFuncSetAttribute(gemm_mma<2>, cudaFuncAttributeMaxDynamicSharedMemorySize, SMEM_GEMM);
        cudaFuncSetAttribute(gemm_mma<3>, cudaFuncAttributeMaxDynamicSharedMemorySize, SMEM_GEMM);
        cudaStreamCreateWithFlags(&s_w, cudaStreamNonBlocking);
        cudaStreamCreateWithFlags(&s_b2, cudaStreamNonBlocking);
        cudaEventCreateWithFlags(&ev_root, cudaEventDisableTiming);
        cudaEventCreateWithFlags(&ev_cvt, cudaEventDisableTiming);
        cudaEventCreateWithFlags(&ev_wo, cudaEventDisableTiming);
        cudaEventCreateWithFlags(&ev_w1, cudaEventDisableTiming);
        cudaEventCreateWithFlags(&ev_w2, cudaEventDisableTiming);
        cudaEventCreateWithFlags(&ev_done1, cudaEventDisableTiming);
    }

    void* p;
    cudaGetSymbolAddress(&p, g_xh);   __half* xh   = (__half*)p;
    cudaGetSymbolAddress(&p, g_wq);   __half* wq   = (__half*)p;
    cudaGetSymbolAddress(&p, g_wo);   __half* wo   = (__half*)p;
    cudaGetSymbolAddress(&p, g_w1);   __half* w1   = (__half*)p;
    cudaGetSymbolAddress(&p, g_w2);   __half* w2   = (__half*)p;
    cudaGetSymbolAddress(&p, g_qkvh); __half* qkvh = (__half*)p;
    cudaGetSymbolAddress(&p, g_ah);   __half* ah   = (__half*)p;
    cudaGetSymbolAddress(&p, g_res1); float* res1  = (float*)p;
    cudaGetSymbolAddress(&p, g_hf);   float* hf    = (float*)p;
    cudaGetSymbolAddress(&p, g_hh);   __half* hh   = (__half*)p;
    cudaGetSymbolAddress(&p, g_fh);   __half* fh   = (__half*)p;
    cudaGetSymbolAddress(&p, g_res2); float* res2  = (float*)p;

    cudaEventRecord(ev_root, 0);

    // side stream: later-needed weight conversions
    cudaStreamWaitEvent(s_w, ev_root, 0);
    to_half<<<(EE * EE / 8 + 255) / 256, 256, 0, s_w>>>(Wo, wo, (size_t)EE * EE / 8);
    cudaEventRecord(ev_wo, s_w);
    to_half<<<(HID * EE / 8 + 255) / 256, 256, 0, s_w>>>(W1, w1, (size_t)HID * EE / 8);
    cudaEventRecord(ev_w1, s_w);
    to_half<<<(EE * HID / 8 + 255) / 256, 256, 0, s_w>>>(W2, w2, (size_t)EE * HID / 8);
    cudaEventRecord(ev_w2, s_w);

    // main stream: fused x + Wqkv conversion (one launch)
    {
        const size_t a8 = (size_t)MM * EE / 8;
        const size_t b8 = (size_t)3 * EE * EE / 8;
        to_half2<<<(unsigned)((a8 + b8 + 255) / 256), 256>>>(x, xh, a8, Wqkv, wq, b8);
    }
    cudaEventRecord(ev_cvt, 0);
    cudaStreamWaitEvent(s_b2, ev_cvt, 0);

    // 2 chunks of 4096 rows; chunk 0 on default stream, chunk 1 on s_b2.
    for (int c = 0; c < 2; ++c) {
        cudaStream_t st = c ? s_b2 : 0;
        const size_t rE  = (size_t)c * CH * EE;
        const size_t r3E = (size_t)c * CH * 3 * EE;
        const size_t rH  = (size_t)c * CH * HID;

        // tile counts (ntx = N/128, ntiles = ntx * M/128)
        const int ntx_qkv = 24, nt_qkv = 24 * (CH / 128);   // 768
        const int ntx_e   = 8,  nt_e   = 8 * (CH / 128);    // 256
        const int ntx_h   = 32, nt_h   = 32 * (CH / 128);   // 1024

        // 1) QKV projection -> fp16 (persistent)
        gemm_mma<3><<<PERSIST_GRID, 256, SMEM_GEMM, st>>>(
            xh + rE, wq, bqkv, nullptr, nullptr, qkvh + r3E, 3 * EE, EE, ntx_qkv, nt_qkv);
        // 2) attention + scrambled reshape (batch-local within chunk)
        attn_kernel<<<CH, 128, 0, st>>>(qkvh + r3E, ah + rE);
        // 3) output projection + residual(x) (persistent)
        cudaStreamWaitEvent(st, ev_wo, 0);
        gemm_mma<2><<<nt_e < PERSIST_GRID ? nt_e : PERSIST_GRID, 256, SMEM_GEMM, st>>>(
            ah + rE, wo, bo, x + rE, res1 + rE, nullptr, EE, EE, ntx_e, nt_e);
        // 4) LN1
        ln_kernel<true><<<CH, 256, 0, st>>>(res1 + rE, ln1_g, ln1_b, hf + rE, hh + rE);
        // 5) FFN up + GELU (persistent)
        cudaStreamWaitEvent(st, ev_w1, 0);
        gemm_mma<1><<<PERSIST_GRID, 256, SMEM_GEMM, st>>>(
            hh + rE, w1, bf1, nullptr, nullptr, fh + rH, HID, EE, ntx_h, nt_h);
        // 6) FFN down + residual(h) (persistent)
        cudaStreamWaitEvent(st, ev_w2, 0);
        gemm_mma<2><<<nt_e < PERSIST_GRID ? nt_e : PERSIST_GRID, 256, SMEM_GEMM, st>>>(
            fh + rH, w2, bf2, hf + rE, res2 + rE, nullptr, EE, HID, ntx_e, nt_e);
        // 7) LN2 -> output
        ln_kernel<false><<<CH, 256, 0, st>>>(res2 + rE, ln2_g, ln2_b, out + rE, nullptr);
    }
    cudaEventRecord(ev_done1, s_b2);
    cudaStreamWaitEvent(0, ev_done1, 0);
}

// round 15
// speedup vs baseline: 1.0236x; 1.0236x over previous
#include <cuda_runtime.h>
#include <cuda_fp16.h>
#include <math.h>
#include <stdint.h>

// ---------------- problem constants ----------------
#define EE   1024
#define HID  4096
#define MM   8192            // B*N rows
#define CH   4096            // rows per chunk (2 batches; attention is batch-local)

// ---------------- scratch (device globals; no allocation) ----------------
__device__ __align__(128) __half g_xh  [(size_t)MM * EE];
__device__ __align__(128) __half g_wq  [(size_t)3 * EE * EE];
__device__ __align__(128) __half g_wo  [(size_t)EE * EE];
__device__ __align__(128) __half g_w1  [(size_t)HID * EE];
__device__ __align__(128) __half g_w2  [(size_t)EE * HID];
__device__ __align__(128) __half g_qkvh[(size_t)MM * 3 * EE];
__device__ __align__(128) __half g_ah  [(size_t)MM * EE];
__device__ __align__(128) float  g_res1[(size_t)MM * EE];
__device__ __align__(128) float  g_hf  [(size_t)MM * EE];
__device__ __align__(128) __half g_hh  [(size_t)MM * EE];
__device__ __align__(128) __half g_fh  [(size_t)MM * HID];
__device__ __align__(128) float  g_res2[(size_t)MM * EE];

// ---------------- helpers ----------------
__device__ __forceinline__ void ldsm4(uint32_t& r0, uint32_t& r1, uint32_t& r2, uint32_t& r3,
                                      uint32_t a) {
    asm volatile("ldmatrix.sync.aligned.m8n8.x4.shared.b16 {%0,%1,%2,%3}, [%4];"
                 : "=r"(r0), "=r"(r1), "=r"(r2), "=r"(r3) : "r"(a));
}
__device__ __forceinline__ void mma16816(float* c, const uint32_t* a, const uint32_t* b) {
    asm volatile(
        "mma.sync.aligned.m16n8k16.row.col.f32.f16.f16.f32 "
        "{%0,%1,%2,%3}, {%4,%5,%6,%7}, {%8,%9}, {%0,%1,%2,%3};"
        : "+f"(c[0]), "+f"(c[1]), "+f"(c[2]), "+f"(c[3])
        : "r"(a[0]), "r"(a[1]), "r"(a[2]), "r"(a[3]), "r"(b[0]), "r"(b[1]));
}
__device__ __forceinline__ void cp16(uint32_t dst, const void* src) {
    asm volatile("cp.async.cg.shared.global [%0], [%1], 16;" :: "r"(dst), "l"(src));
}
__device__ __forceinline__ void cp_commit() { asm volatile("cp.async.commit_group;"); }
template <int N>
__device__ __forceinline__ void cp_wait() { asm volatile("cp.async.wait_group %0;" :: "n"(N)); }

// swizzled 16B-chunk offset within [rows x 64half] smem region (row-major 128B rows)
__device__ __forceinline__ uint32_t swoff(uint32_t r, uint32_t c) {
    return ((r << 3) + (c ^ (r & 7))) << 4;
}

// ---------------- fp32 -> fp16 conversion (single region) ----------------
__global__ __launch_bounds__(256) void to_half(
    const float* __restrict__ src, __half* __restrict__ dst, size_t total8)
{
    size_t idx = (size_t)blockIdx.x * blockDim.x + threadIdx.x;
    if (idx >= total8) return;
    const float4 v0 = reinterpret_cast<const float4*>(src)[idx * 2];
    const float4 v1 = reinterpret_cast<const float4*>(src)[idx * 2 + 1];
    __align__(16) __half hh[8];
    hh[0] = __float2half_rn(v0.x); hh[1] = __float2half_rn(v0.y);
    hh[2] = __float2half_rn(v0.z); hh[3] = __float2half_rn(v0.w);
    hh[4] = __float2half_rn(v1.x); hh[5] = __float2half_rn(v1.y);
    hh[6] = __float2half_rn(v1.z); hh[7] = __float2half_rn(v1.w);
    reinterpret_cast<uint4*>(dst)[idx] = *reinterpret_cast<uint4*>(hh);
}

// ---------------- fused fp32 -> fp16 conversion (two regions, one launch) ----------------
__global__ __launch_bounds__(256) void to_half2(
    const float* __restrict__ sa, __half* __restrict__ da, size_t a8,
    const float* __restrict__ sb, __half* __restrict__ db, size_t b8)
{
    size_t idx = (size_t)blockIdx.x * blockDim.x + threadIdx.x;
    const float* src; __half* dst;
    if (idx < a8)            { src = sa; dst = da; }
    else if (idx < a8 + b8)  { src = sb; dst = db; idx -= a8; }
    else return;
    const float4 v0 = reinterpret_cast<const float4*>(src)[idx * 2];
    const float4 v1 = reinterpret_cast<const float4*>(src)[idx * 2 + 1];
    __align__(16) __half hh[8];
    hh[0] = __float2half_rn(v0.x); hh[1] = __float2half_rn(v0.y);
    hh[2] = __float2half_rn(v0.z); hh[3] = __float2half_rn(v0.w);
    hh[4] = __float2half_rn(v1.x); hh[5] = __float2half_rn(v1.y);
    hh[6] = __float2half_rn(v1.z); hh[7] = __float2half_rn(v1.w);
    reinterpret_cast<uint4*>(dst)[idx] = *reinterpret_cast<uint4*>(hh);
}

// ---------------- fp16 tensor-core GEMM: C[M,N] = A[M,K] * B[N,K]^T ----------------
// Tile 128x128, BK=64, 3 stages, 2 CTAs/SM. 8 warps as 2(M) x 4(N), warp 64x32.
// EPI 1: +bias,GELU -> Ch ; EPI 2: +bias + fp32 res -> Cf ; EPI 3: +bias -> Ch
#define STG_BYTES 32768
#define SMEM_GEMM (3 * STG_BYTES)

template <int EPI>
__global__ __launch_bounds__(256, 2) void gemm_mma(
    const __half* __restrict__ A, const __half* __restrict__ B,
    const float* __restrict__ bias, const float* __restrict__ res,
    float* __restrict__ Cf, __half* __restrict__ Ch,
    int N, int K)
{
    extern __shared__ __align__(128) char smem[];
    const uint32_t sb = (uint32_t)__cvta_generic_to_shared(smem);

    const int tid  = threadIdx.x;
    const int lane = tid & 31;
    const int wid  = tid >> 5;
    const int wm   = wid & 1;
    const int wn   = wid >> 1;
    const int mblk = blockIdx.y * 128;
    const int nblk = blockIdx.x * 128;

    float acc[4][4][4];
#pragma unroll
    for (int i = 0; i < 4; ++i)
#pragma unroll
        for (int j = 0; j < 4; ++j)
#pragma unroll
            for (int q = 0; q < 4; ++q) acc[i][j][q] = 0.f;

    const int T = K >> 6;

    auto load_stage = [&](int s, int kc) {
        const uint32_t base = sb + s * STG_BYTES;
        const int k0 = kc * 64;
#pragma unroll
        for (int i = 0; i < 4; ++i) {               // A: 128 rows
            const int id  = tid + i * 256;
            const int row = id >> 3;
            const int c   = id & 7;
            cp16(base + swoff(row, c), A + (size_t)(mblk + row) * K + k0 + c * 8);
        }
#pragma unroll
        for (int i = 0; i < 4; ++i) {               // B: 128 rows
            const int id  = tid + i * 256;
            const int row = id >> 3;
            const int c   = id & 7;
            cp16(base + 16384 + swoff(row, c), B + (size_t)(nblk + row) * K + k0 + c * 8);
        }
    };

    load_stage(0, 0); cp_commit();
    load_stage(1, 1); cp_commit();

    for (int t = 0; t < T; ++t) {
        if (t + 1 < T) load_stage((t + 1) & 1 ? (t + 1) % 3 : (t + 1) % 3, t + 1), (void)0;
        // NOTE: schedule identical to R11: prefetch t+2 below
        break;
    }
    // R11 mainloop (two barriers, prefetch depth 2)
    for (int t = 0; t < T; ++t) {
        if (t + 2 < T) load_stage((t + 2) % 3, t + 2);
        cp_commit();
        cp_wait<2>();
        __syncthreads();

        const uint32_t stA = sb + (t % 3) * STG_BYTES;
        const uint32_t stB = stA + 16384;

#pragma unroll
        for (int ks = 0; ks < 4; ++ks) {
            uint32_t a[4][4], b[4][2];
            const uint32_t arow = wm * 64 + (lane & 15);
            const uint32_t acol = ks * 2 + (lane >> 4);
#pragma unroll
            for (int mi = 0; mi < 4; ++mi) {
                const uint32_t off = swoff(arow + mi * 16, acol);
                ldsm4(a[mi][0], a[mi][1], a[mi][2], a[mi][3], stA + off);
            }
            const uint32_t brow = wn * 32 + (lane & 7) + ((lane >> 4) << 3);
            const uint32_t bcol = ks * 2 + ((lane >> 3) & 1);
#pragma unroll
            for (int pi = 0; pi < 2; ++pi) {
                const uint32_t off = swoff(brow + pi * 16, bcol);
                ldsm4(b[2 * pi][0], b[2 * pi][1], b[2 * pi + 1][0], b[2 * pi + 1][1],
                      stB + off);
            }
#pragma unroll
            for (int mi = 0; mi < 4; ++mi)
#pragma unroll
                for (int ni = 0; ni < 4; ++ni) mma16816(acc[mi][ni], a[mi], b[ni]);
        }
        __syncthreads();
    }
    cp_wait<0>();

    // -------- epilogue --------
#pragma unroll
    for (int mi = 0; mi < 4; ++mi) {
#pragma unroll
        for (int ni = 0; ni < 4; ++ni) {
            const int n = nblk + wn * 32 + ni * 8 + (lane & 3) * 2;
            const float b0 = bias[n], b1 = bias[n + 1];
            const int m0 = mblk + wm * 64 + mi * 16 + (lane >> 2);
#pragma unroll
            for (int half = 0; half < 2; ++half) {
                const int m = m0 + half * 8;
                float v0 = acc[mi][ni][half * 2 + 0] + b0;
                float v1 = acc[mi][ni][half * 2 + 1] + b1;
                if (EPI == 2) {
                    const float2 rv = *reinterpret_cast<const float2*>(res + (size_t)m * N + n);
                    v0 += rv.x; v1 += rv.y;
                    *reinterpret_cast<float2*>(Cf + (size_t)m * N + n) = make_float2(v0, v1);
                } else {
                    if (EPI == 1) {
                        v0 = 0.5f * v0 * (1.0f + erff(v0 * 0.70710678118654752f));
                        v1 = 0.5f * v1 * (1.0f + erff(v1 * 0.70710678118654752f));
                    }
                    __half2 h2;
                    h2.x = __float2half_rn(v0);
                    h2.y = __float2half_rn(v1);
                    *reinterpret_cast<__half2*>(Ch + (size_t)m * N + n) = h2;
                }
            }
        }
    }
}

// ---------------- per-token head-softmax attention, 2 tokens per block ----------------
// blockDim = 256: threads [0,128) handle token 2*blockIdx.x, [128,256) token +1.
// Control flow is symmetric across halves, so block-wide __syncthreads is legal.
__global__ __launch_bounds__(256) void attn_kernel(
    const __half* __restrict__ qkv, __half* __restrict__ ahi)
{
    __shared__ float sq[2][3 * EE];
    __shared__ float sa[2][16][17];

    const int half_id = threadIdx.x >> 7;        // 0 or 1
    const int tid     = threadIdx.x & 127;       // lane within token group
    const int loc     = blockIdx.x * 2 + half_id; // local row in chunk
    const int bb      = loc >> 11;               // batch within chunk
    const int t       = loc & 2047;              // token within batch

    float* sqh = sq[half_id];

    const uint4* src = reinterpret_cast<const uint4*>(qkv + (size_t)loc * (3 * EE));
#pragma unroll
    for (int i = tid; i < 384; i += 128) {
        const uint4 pk = src[i];
        const __half* hp = reinterpret_cast<const __half*>(&pk);
        float* dp = sqh + i * 8;
#pragma unroll
        for (int j = 0; j < 8; ++j) dp[j] = __half2float(hp[j]);
    }
    __syncthreads();

#pragma unroll
    for (int e = tid; e < 256; e += 128) {
        const int i = e >> 4, j = e & 15;
        const float* qi = sqh + i * 64;
        const float* kj = sqh + EE + j * 64;
        float dot = 0.f;
#pragma unroll
        for (int d = 0; d < 64; ++d) dot += qi[d] * kj[d];
        sa[half_id][i][j] = dot * 0.03125f;   // / sqrt(E)=32
    }
    __syncthreads();

    if (tid < 16) {
        float mx = -1e30f;
#pragma unroll
        for (int j = 0; j < 16; ++j) mx = fmaxf(mx, sa[half_id][tid][j]);
        float ex[16], s = 0.f;
#pragma unroll
        for (int j = 0; j < 16; ++j) { ex[j] = expf(sa[half_id][tid][j] - mx); s += ex[j]; }
        const float inv = 1.0f / s;
#pragma unroll
        for (int j = 0; j < 16; ++j) sa[half_id][tid][j] = ex[j] * inv;
    }
    __syncthreads();

    const int i  = tid >> 3;
    const int db = (tid & 7) * 8;
    float o[8] = {0.f, 0.f, 0.f, 0.f, 0.f, 0.f, 0.f, 0.f};
#pragma unroll
    for (int j = 0; j < 16; ++j) {
        const float a = sa[half_id][i][j];
        const float* vj = sqh + 2 * EE + j * 64 + db;
#pragma unroll
        for (int p = 0; p < 8; ++p) o[p] += a * vj[p];
    }
    // scrambled target within batch: row = i*128 + t/16, col = (t%16)*64 + db
    const int m = bb * 2048 + i * 128 + (t >> 4);
    const int c = ((t & 15) << 6) + db;
    __align__(16) __half hh[8];
#pragma unroll
    for (int p = 0; p < 8; ++p) hh[p] = __float2half_rn(o[p]);
    *reinterpret_cast<uint4*>(ahi + (size_t)m * EE + c) = *reinterpret_cast<uint4*>(hh);
}

// ---------------- row LayerNorm over 1024 fp32 inputs ----------------
template <bool EMIT_HALF>
__global__ __launch_bounds__(256) void ln_kernel(
    const float* __restrict__ in, const float* __restrict__ g, const float* __restrict__ b,
    float* __restrict__ outf, __half* __restrict__ oh)
{
    __shared__ float red[8];
    __shared__ float s_mean, s_rstd;
    const int row = blockIdx.x;
    const int tid = threadIdx.x;

    const float4 v = reinterpret_cast<const float4*>(in + (size_t)row * EE)[tid];

    float s = v.x + v.y + v.z + v.w;
#pragma unroll
    for (int o = 16; o; o >>= 1) s += __shfl_xor_sync(0xffffffffu, s, o);
    if ((tid & 31) == 0) red[tid >> 5] = s;
    __syncthreads();
    if (tid == 0) {
        float tt = 0.f;
#pragma unroll
        for (int i = 0; i < 8; ++i) tt += red[i];
        s_mean = tt * (1.0f / 1024.0f);
    }
    __syncthreads();
    const float mean = s_mean;

    const float dx = v.x - mean, dy = v.y - mean, dz = v.z - mean, dw = v.w - mean;
    float sq = dx * dx + dy * dy + dz * dz + dw * dw;
#pragma unroll
    for (int o = 16; o; o >>= 1) sq += __shfl_xor_sync(0xffffffffu, sq, o);
    if ((tid & 31) == 0) red[tid >> 5] = sq;
    __syncthreads();
    if (tid == 0) {
        float tt = 0.f;
#pragma unroll
        for (int i = 0; i < 8; ++i) tt += red[i];
        s_rstd = rsqrtf(tt * (1.0f / 1024.0f) + 1e-5f);
    }
    __syncthreads();
    const float rstd = s_rstd;

    const float4 gg = reinterpret_cast<const float4*>(g)[tid];
    const float4 bb = reinterpret_cast<const float4*>(b)[tid];
    float4 o4;
    o4.x = dx * rstd * gg.x + bb.x;
    o4.y = dy * rstd * gg.y + bb.y;
    o4.z = dz * rstd * gg.z + bb.z;
    o4.w = dw * rstd * gg.w + bb.w;
    reinterpret_cast<float4*>(outf + (size_t)row * EE)[tid] = o4;

    if (EMIT_HALF) {
        __align__(8) __half hh4[4];
        hh4[0] = __float2half_rn(o4.x); hh4[1] = __float2half_rn(o4.y);
        hh4[2] = __float2half_rn(o4.z); hh4[3] = __float2half_rn(o4.w);
        *reinterpret_cast<uint2*>(oh + (size_t)row * EE + tid * 4) =
            *reinterpret_cast<uint2*>(hh4);
    }
}

// ---------------- launcher ----------------
extern "C" void kernel_launch(void* const* d_in, const int* in_sizes, int n_in,
                              void* d_out, int out_size)
{
    (void)in_sizes; (void)n_in; (void)out_size;
    const float* x     = (const float*)d_in[0];
    const float* Wqkv  = (const float*)d_in[1];
    const float* bqkv  = (const float*)d_in[2];
    const float* Wo    = (const float*)d_in[3];
    const float* bo    = (const float*)d_in[4];
    const float* ln1_g = (const float*)d_in[5];
    const float* ln1_b = (const float*)d_in[6];
    const float* W1    = (const float*)d_in[7];
    const float* bf1   = (const float*)d_in[8];
    const float* W2    = (const float*)d_in[9];
    const float* bf2   = (const float*)d_in[10];
    const float* ln2_g = (const float*)d_in[11];
    const float* ln2_b = (const float*)d_in[12];
    float* out = (float*)d_out;

    static cudaStream_t s_w = nullptr, s_b2 = nullptr;
    static cudaEvent_t ev_root, ev_cvt, ev_wo, ev_w1, ev_w2, ev_done1;
    if (!s_w) {
        cudaFuncSetAttribute(gemm_mma<1>, cudaFuncAttributeMaxDynamicSharedMemorySize, SMEM_GEMM);
        cudaFuncSetAttribute(gemm_mma<2>, cudaFuncAttributeMaxDynamicSharedMemorySize, SMEM_GEMM);
        cudaFuncSetAttribute(gemm_mma<3>, cudaFuncAttributeMaxDynamicSharedMemorySize, SMEM_GEMM);
        cudaStreamCreateWithFlags(&s_w, cudaStreamNonBlocking);
        cudaStreamCreateWithFlags(&s_b2, cudaStreamNonBlocking);
        cudaEventCreateWithFlags(&ev_root, cudaEventDisableTiming);
        cudaEventCreateWithFlags(&ev_cvt, cudaEventDisableTiming);
        cudaEventCreateWithFlags(&ev_wo, cudaEventDisableTiming);
        cudaEventCreateWithFlags(&ev_w1, cudaEventDisableTiming);
        cudaEventCreateWithFlags(&ev_w2, cudaEventDisableTiming);
        cudaEventCreateWithFlags(&ev_done1, cudaEventDisableTiming);
    }

    void* p;
    cudaGetSymbolAddress(&p, g_xh);   __half* xh   = (__half*)p;
    cudaGetSymbolAddress(&p, g_wq);   __half* wq   = (__half*)p;
    cudaGetSymbolAddress(&p, g_wo);   __half* wo   = (__half*)p;
    cudaGetSymbolAddress(&p, g_w1);   __half* w1   = (__half*)p;
    cudaGetSymbolAddress(&p, g_w2);   __half* w2   = (__half*)p;
    cudaGetSymbolAddress(&p, g_qkvh); __half* qkvh = (__half*)p;
    cudaGetSymbolAddress(&p, g_ah);   __half* ah   = (__half*)p;
    cudaGetSymbolAddress(&p, g_res1); float* res1  = (float*)p;
    cudaGetSymbolAddress(&p, g_hf);   float* hf    = (float*)p;
    cudaGetSymbolAddress(&p, g_hh);   __half* hh   = (__half*)p;
    cudaGetSymbolAddress(&p, g_fh);   __half* fh   = (__half*)p;
    cudaGetSymbolAddress(&p, g_res2); float* res2  = (float*)p;

    cudaEventRecord(ev_root, 0);

    // side stream: later-needed weight conversions
    cudaStreamWaitEvent(s_w, ev_root, 0);
    to_half<<<(EE * EE / 8 + 255) / 256, 256, 0, s_w>>>(Wo, wo, (size_t)EE * EE / 8);
    cudaEventRecord(ev_wo, s_w);
    to_half<<<(HID * EE / 8 + 255) / 256, 256, 0, s_w>>>(W1, w1, (size_t)HID * EE / 8);
    cudaEventRecord(ev_w1, s_w);
    to_half<<<(EE * HID / 8 + 255) / 256, 256, 0, s_w>>>(W2, w2, (size_t)EE * HID / 8);
    cudaEventRecord(ev_w2, s_w);

    // main stream: fused x + Wqkv conversion (one launch)
    {
        const size_t a8 = (size_t)MM * EE / 8;
        const size_t b8 = (size_t)3 * EE * EE / 8;
        to_half2<<<(unsigned)((a8 + b8 + 255) / 256), 256>>>(x, xh, a8, Wqkv, wq, b8);
    }
    cudaEventRecord(ev_cvt, 0);
    cudaStreamWaitEvent(s_b2, ev_cvt, 0);

    // 2 chunks of 4096 rows; chunk 0 on default stream, chunk 1 on s_b2
    for (int c = 0; c < 2; ++c) {
        cudaStream_t st = c ? s_b2 : 0;
        const size_t rE  = (size_t)c * CH * EE;
        const size_t r3E = (size_t)c * CH * 3 * EE;
        const size_t rH  = (size_t)c * CH * HID;

        // 1) QKV projection -> fp16
        gemm_mma<3><<<dim3(24, CH / 128), 256, SMEM_GEMM, st>>>(
            xh + rE, wq, bqkv, nullptr, nullptr, qkvh + r3E, 3 * EE, EE);
        // 2) attention + scrambled reshape (2 tokens/block)
        attn_kernel<<<CH / 2, 256, 0, st>>>(qkvh + r3E, ah + rE);
        // 3) output projection + residual(x)
        cudaStreamWaitEvent(st, ev_wo, 0);
        gemm_mma<2><<<dim3(8, CH / 128), 256, SMEM_GEMM, st>>>(
            ah + rE, wo, bo, x + rE, res1 + rE, nullptr, EE, EE);
        // 4) LN1
        ln_kernel<true><<<CH, 256, 0, st>>>(res1 + rE, ln1_g, ln1_b, hf + rE, hh + rE);
        // 5) FFN up + GELU
        cudaStreamWaitEvent(st, ev_w1, 0);
        gemm_mma<1><<<dim3(32, CH / 128), 256, SMEM_GEMM, st>>>(
            hh + rE, w1, bf1, nullptr, nullptr, fh + rH, HID, EE);
        // 6) FFN down + residual(h)
        cudaStreamWaitEvent(st, ev_w2, 0);
        gemm_mma<2><<<dim3(8, CH / 128), 256, SMEM_GEMM, st>>>(
            fh + rH, w2, bf2, hf + rE, res2 + rE, nullptr, EE, HID);
        // 7) LN2 -> output
        ln_kernel<false><<<CH, 256, 0, st>>>(res2 + rE, ln2_g, ln2_b, out + rE, nullptr);
    }
    cudaEventRecord(ev_done1, s_b2);
    cudaStreamWaitEvent(0, ev_done1, 0);
}